// round 13
// baseline (speedup 1.0000x reference)
#include <cuda_runtime.h>
#include <cuda_bf16.h>
#include <cstdint>
#include <cstddef>

// ---------------------------------------------------------------------------
// pre[b,o,d] = sum_{h,f} W[o, h*64+f] * x[b,h,d] * inp[b,f,d] + bias[o]
// x_next = relu(pre);  out[:, off+o] = sum_d relu(pre);  3 chained layers.
// B=512, F=64, D=32, O=128.
//
// GEMM per layer: D[o=128, n=(b*32+d)] = W[o,k] * Z[k,n], Z built in SMEM.
// mma.sync m16n8k16 bf16, 3-MMA split (Whi*Zhi + Whi*Zlo + Wlo*Zhi).
// Layer 0 uses the symmetry fold (K 4096 -> 2112).
// Round-13: m64 x n64 consumer warp tiles (4 consumers + 2 producers, 192
// threads). Halves redundant B-fragment LDSM traffic on the smem crossbar
// (the suspected residual bottleneck) and doubles per-warp MMA ILP.
// ---------------------------------------------------------------------------

#define SW128(o) ((o) ^ (((o) >> 3) & 0x70))

#define K0SYM   2112          // padded folded K for layer 0 (33 tiles)
#define K0REAL  2080          // 64*65/2 real pairs

__device__ __align__(16) float g_x1[512 * 128 * 32];
__device__ __align__(16) float g_x2[512 * 128 * 32];
__device__ uint4 g_W0[33 * 32768 / 16];          // folded layer-0 tiles
__device__ uint4 g_W1[128 * 8192 * 4 / 16];
__device__ uint4 g_W2[128 * 8192 * 4 / 16];
__device__ unsigned short g_pair[K0SYM];         // k -> (i | j<<8)

__device__ __forceinline__ uint32_t smem_u32(const void* p) {
    uint32_t a;
    asm("{ .reg .u64 t; cvta.to.shared.u64 t, %1; cvt.u32.u64 %0, t; }"
        : "=r"(a) : "l"(p));
    return a;
}

__device__ __forceinline__ void split2(float z0, float z1,
                                       uint32_t& hi, uint32_t& lo) {
    __nv_bfloat162 h = __floats2bfloat162_rn(z0, z1);
    float2 hf = __bfloat1622float2(h);
    __nv_bfloat162 l = __floats2bfloat162_rn(z0 - hf.x, z1 - hf.y);
    hi = reinterpret_cast<uint32_t&>(h);
    lo = reinterpret_cast<uint32_t&>(l);
}

__device__ __forceinline__ void ldsm4(uint32_t r[4], uint32_t addr) {
    asm volatile("ldmatrix.sync.aligned.m8n8.x4.shared.b16 {%0,%1,%2,%3}, [%4];"
                 : "=r"(r[0]), "=r"(r[1]), "=r"(r[2]), "=r"(r[3]) : "r"(addr));
}

__device__ __forceinline__ void mma_bf16(float c[4], const uint32_t a[4],
                                         uint32_t b0, uint32_t b1) {
    asm volatile(
        "mma.sync.aligned.m16n8k16.row.col.f32.bf16.bf16.f32 "
        "{%0,%1,%2,%3}, {%4,%5,%6,%7}, {%8,%9}, {%0,%1,%2,%3};"
        : "+f"(c[0]), "+f"(c[1]), "+f"(c[2]), "+f"(c[3])
        : "r"(a[0]), "r"(a[1]), "r"(a[2]), "r"(a[3]), "r"(b0), "r"(b1));
}

// --------------------------- mbarrier helpers -------------------------------
#define MBAR_INIT(a, c) \
    asm volatile("mbarrier.init.shared.b64 [%0], %1;" :: "r"(a), "r"(c) : "memory")
#define MBAR_ARRIVE(a) \
    asm volatile("mbarrier.arrive.release.cta.shared::cta.b64 _, [%0];" :: "r"(a) : "memory")
#define MBAR_WAIT(a, p) do { uint32_t _m = (a); uint32_t _p = (p); uint32_t _d;      \
    asm volatile("{\n\t.reg .pred q;\n\t"                                            \
        "mbarrier.try_wait.parity.acquire.cta.shared::cta.b64 q, [%1], %2;\n\t"      \
        "selp.b32 %0,1,0,q;\n\t}" : "=r"(_d) : "r"(_m), "r"(_p) : "memory");         \
    if (!_d) {                                                                       \
        asm volatile("{\n\t.reg .pred q;\n\t"                                        \
            "WL%=:\n\t"                                                              \
            "mbarrier.try_wait.parity.acquire.cta.shared::cta.b64 q, [%0], %1, 0x989680;\n\t" \
            "@q bra.uni WD%=;\n\t"                                                   \
            "bra.uni WL%=;\n\t"                                                      \
            "WD%=:\n\t}" :: "r"(_m), "r"(_p) : "memory");                            \
    } } while (0)

// --------------------------- pair table (k -> (i,j), i<=j) ------------------
__global__ void init_pairs() {
    int k = blockIdx.x * 256 + threadIdx.x;
    if (k >= K0SYM) return;
    if (k < K0REAL) {
        int i = 0, base = 0;
        while (base + (64 - i) <= k) { base += 64 - i; i++; }
        int j = i + (k - base);
        g_pair[k] = (unsigned short)(i | (j << 8));
    } else {
        g_pair[k] = 0;
    }
}

// --------------------------- W prep: fp32 -> split bf16 tiles ---------------
__global__ __launch_bounds__(256)
void prep_w(const float* __restrict__ W, uint4* __restrict__ dst, int K) {
    int idx = blockIdx.x * 256 + threadIdx.x;
    int cpr = K >> 3;
    if (idx >= 128 * cpr) return;
    int o = idx / cpr;
    int k = (idx % cpr) * 8;
    const float4* src = (const float4*)(W + (size_t)o * K + k);
    float4 v0 = src[0], v1 = src[1];
    float zf[8] = {v0.x, v0.y, v0.z, v0.w, v1.x, v1.y, v1.z, v1.w};
    uint32_t hi[4], lo[4];
#pragma unroll
    for (int p = 0; p < 4; p++) split2(zf[2 * p], zf[2 * p + 1], hi[p], lo[p]);
    char* base = (char*)dst + (size_t)(k >> 6) * 32768;
    uint32_t off = SW128((uint32_t)(o * 128 + (k & 63) * 2));
    *(uint4*)(base + off)         = make_uint4(hi[0], hi[1], hi[2], hi[3]);
    *(uint4*)(base + 16384 + off) = make_uint4(lo[0], lo[1], lo[2], lo[3]);
}

// Folded layer-0 prep
__global__ __launch_bounds__(256)
void prep_w0_sym(const float* __restrict__ W, uint4* __restrict__ dst) {
    int idx = blockIdx.x * 256 + threadIdx.x;
    if (idx >= 128 * (K0SYM / 8)) return;
    int o = idx / (K0SYM / 8);
    int k0 = (idx % (K0SYM / 8)) * 8;
    const float* Wo = W + (size_t)o * 4096;
    float zf[8];
#pragma unroll
    for (int t = 0; t < 8; t++) {
        int k = k0 + t;
        float c = 0.f;
        if (k < K0REAL) {
            int pr = g_pair[k];
            int i = pr & 255, j = pr >> 8;
            c = (i == j) ? Wo[i * 65] : (Wo[i * 64 + j] + Wo[j * 64 + i]);
        }
        zf[t] = c;
    }
    uint32_t hi[4], lo[4];
#pragma unroll
    for (int p = 0; p < 4; p++) split2(zf[2 * p], zf[2 * p + 1], hi[p], lo[p]);
    char* base = (char*)dst + (size_t)(k0 >> 6) * 32768;
    uint32_t off = SW128((uint32_t)(o * 128 + (k0 & 63) * 2));
    *(uint4*)(base + off)         = make_uint4(hi[0], hi[1], hi[2], hi[3]);
    *(uint4*)(base + 16384 + off) = make_uint4(lo[0], lo[1], lo[2], lo[3]);
}

// --------------------------- main layer kernel ------------------------------
// SMEM: [0,32768) inp_s; [32768 + s*65536), s=0..2: Whi Wlo Zhi Zlo (64K each)
//       [229376,229424): mbarriers full0..2, empty0..2
#define STAGE_OFF  32768
#define MB_OFF     229376
#define SMEM_TOTAL 229440

template <int NTILES, int H, bool SYM, bool WRITE_NEXT>
__global__ __launch_bounds__(192, 1)
void layer_mma(const float* __restrict__ x,
               const float* __restrict__ inp,
               const uint4* __restrict__ Wsp,
               const float* __restrict__ bias,
               float* __restrict__ x_next,
               float* __restrict__ out,
               int out_off)
{
    extern __shared__ char smem[];
    const uint32_t sb = smem_u32(smem);
    float* inp_s = (float*)smem;
    const int tid  = threadIdx.x;
    const int lane = tid & 31;
    const int w    = tid >> 5;
    const int b0   = blockIdx.x * 4;

    const uint32_t FULLB  = sb + MB_OFF;        // FULLB + 8*s
    const uint32_t EMPTYB = sb + MB_OFF + 24;   // EMPTYB + 8*s

    if (tid == 0) {
#pragma unroll
        for (int s = 0; s < 3; s++) {
            MBAR_INIT(FULLB + 8 * s, 2);     // 2 producer warps
            MBAR_INIT(EMPTYB + 8 * s, 4);    // 4 consumer warps
        }
    }

    {   // stage inp (8192 floats = 2048 float4, 192 threads)
        const float4* src = (const float4*)(inp + (size_t)b0 * 2048);
        float4* dst = (float4*)inp_s;
        for (int i = tid; i < 2048; i += 192) dst[i] = src[i];
    }
    __syncthreads();   // inp_s + mbarriers ready

    if (w >= 4) {
        // ==================== PRODUCERS (warps 4-5) ====================
        const int ptid = tid - 128;                // 0..63; handles n, n+64
        const char* gW = (const char*)Wsp;

        for (int it = 0; it < NTILES; ++it) {
            const int s = it % 3;
            const int u = it / 3;
            if (it >= 3) MBAR_WAIT(EMPTYB + 8 * s, (uint32_t)((u - 1) & 1));

            // W tile via cp.async: 64 threads x 512 B
            {
                uint32_t dsb = sb + STAGE_OFF + s * 65536 + ptid * 16;
                const char* srcW = gW + (size_t)it * 32768 + ptid * 16;
#pragma unroll
                for (int i = 0; i < 32; i++)
                    asm volatile("cp.async.cg.shared.global [%0], [%1], 16;"
                                 :: "r"(dsb + i * 1024), "l"(srcW + i * 1024));
                asm volatile("cp.async.commit_group;");
            }
            // Z tile: two n-columns per thread, split hi/lo
            char* zp = smem + STAGE_OFF + s * 65536 + 32768;
#pragma unroll
            for (int nn = 0; nn < 2; nn++) {
                const int n  = ptid + nn * 64;
                const int bq = n >> 5;
                const int dd = n & 31;
                const float* ip = inp_s + (size_t)bq * 2048 + dd;
                const uint32_t zrow  = (uint32_t)n * 128;
                const uint32_t zmask = (uint32_t)((n & 7) << 4);
                if (SYM) {
#pragma unroll
                    for (int i = 0; i < 8; i++) {
                        float z[8];
#pragma unroll
                        for (int j = 0; j < 8; j++) {
                            int pr = __ldg(&g_pair[it * 64 + i * 8 + j]);
                            z[j] = ip[(pr & 255) * 32] * ip[(pr >> 8) * 32];
                        }
                        uint32_t hi[4], lo[4];
#pragma unroll
                        for (int p = 0; p < 4; p++)
                            split2(z[2 * p], z[2 * p + 1], hi[p], lo[p]);
                        uint32_t off = zrow + ((16u * i) ^ zmask);
                        *(uint4*)(zp + off)         = make_uint4(hi[0], hi[1], hi[2], hi[3]);
                        *(uint4*)(zp + 16384 + off) = make_uint4(lo[0], lo[1], lo[2], lo[3]);
                    }
                } else {
                    const float xv =
                        __ldg(x + ((size_t)(b0 + bq) * H + it) * 32 + dd);
#pragma unroll
                    for (int i = 0; i < 8; i++) {
                        float z[8];
#pragma unroll
                        for (int j = 0; j < 8; j++) z[j] = xv * ip[(i * 8 + j) * 32];
                        uint32_t hi[4], lo[4];
#pragma unroll
                        for (int p = 0; p < 4; p++)
                            split2(z[2 * p], z[2 * p + 1], hi[p], lo[p]);
                        uint32_t off = zrow + ((16u * i) ^ zmask);
                        *(uint4*)(zp + off)         = make_uint4(hi[0], hi[1], hi[2], hi[3]);
                        *(uint4*)(zp + 16384 + off) = make_uint4(lo[0], lo[1], lo[2], lo[3]);
                    }
                }
            }
            asm volatile("cp.async.wait_group 0;");
            __syncwarp();
            if (lane == 0) MBAR_ARRIVE(FULLB + 8 * s);
        }
        return;   // producers exit
    }

    // ==================== CONSUMERS (warps 0-3), m64 x n64 ====================
    const int wm = w & 1;     // m64 block
    const int wn = w >> 1;    // n64 block

    const int g = lane >> 3;
    const uint32_t maskL = (uint32_t)((lane & 7) << 4);
    uint32_t aRow[4], bRow[4], aCol[4], bCol[4];
#pragma unroll
    for (int mi = 0; mi < 4; mi++)
        aRow[mi] = (uint32_t)((64 * wm + 16 * mi + (lane & 7) + (g & 1) * 8) * 128);
#pragma unroll
    for (int p = 0; p < 4; p++)
        bRow[p] = (uint32_t)((64 * wn + 16 * p + 8 * ((g >> 1) & 1) + (lane & 7)) * 128);
#pragma unroll
    for (int kk = 0; kk < 4; kk++) {
        aCol[kk] = ((uint32_t)(((g >> 1) & 1) * 16 + 32 * kk)) ^ maskL;
        bCol[kk] = ((uint32_t)((g & 1) * 16 + 32 * kk)) ^ maskL;
    }

    float C[4][8][4];
#pragma unroll
    for (int i = 0; i < 4; i++)
#pragma unroll
        for (int j = 0; j < 8; j++)
#pragma unroll
            for (int q = 0; q < 4; q++) C[i][j][q] = 0.f;

    for (int it = 0; it < NTILES; ++it) {
        const int s = it % 3;
        const int u = it / 3;
        MBAR_WAIT(FULLB + 8 * s, (uint32_t)(u & 1));

        const uint32_t st = sb + STAGE_OFF + s * 65536;
#pragma unroll
        for (int kk = 0; kk < 4; kk++) {
            uint32_t ah[4][4], al[4][4], bh[4][4], bl[4][4];
#pragma unroll
            for (int mi = 0; mi < 4; mi++) {
                ldsm4(ah[mi], st + aRow[mi] + aCol[kk]);
                ldsm4(al[mi], st + 16384 + aRow[mi] + aCol[kk]);
            }
#pragma unroll
            for (int p = 0; p < 4; p++) {
                ldsm4(bh[p], st + 32768 + bRow[p] + bCol[kk]);
                ldsm4(bl[p], st + 49152 + bRow[p] + bCol[kk]);
            }
            // term 1: Whi * Zhi -- 32 distinct accumulators
#pragma unroll
            for (int p = 0; p < 4; p++)
#pragma unroll
                for (int mi = 0; mi < 4; mi++)
#pragma unroll
                    for (int q = 0; q < 2; q++)
                        mma_bf16(C[mi][2 * p + q], ah[mi],
                                 bh[p][2 * q], bh[p][2 * q + 1]);
            // term 2: Whi * Zlo
#pragma unroll
            for (int p = 0; p < 4; p++)
#pragma unroll
                for (int mi = 0; mi < 4; mi++)
#pragma unroll
                    for (int q = 0; q < 2; q++)
                        mma_bf16(C[mi][2 * p + q], ah[mi],
                                 bl[p][2 * q], bl[p][2 * q + 1]);
            // term 3: Wlo * Zhi
#pragma unroll
            for (int p = 0; p < 4; p++)
#pragma unroll
                for (int mi = 0; mi < 4; mi++)
#pragma unroll
                    for (int q = 0; q < 2; q++)
                        mma_bf16(C[mi][2 * p + q], al[mi],
                                 bh[p][2 * q], bh[p][2 * q + 1]);
        }
        __syncwarp();
        if (lane == 0) MBAR_ARRIVE(EMPTYB + 8 * s);
    }

    // Epilogue: bias + relu, write x_next, reduce over d -> out
    const int mrow = lane >> 2;
    const int qn   = lane & 3;
#pragma unroll
    for (int mi = 0; mi < 4; mi++) {
#pragma unroll
        for (int h2 = 0; h2 < 2; h2++) {
            const int o = 64 * wm + 16 * mi + 8 * h2 + mrow;
            const float bv = __ldg(bias + o);
#pragma unroll
            for (int bl2 = 0; bl2 < 2; bl2++) {
                const int b = b0 + 2 * wn + bl2;
                float sum = 0.f;
#pragma unroll
                for (int jj = 0; jj < 4; jj++) {
                    const int j = 4 * bl2 + jj;
                    float v0 = fmaxf(C[mi][j][2 * h2]     + bv, 0.f);
                    float v1 = fmaxf(C[mi][j][2 * h2 + 1] + bv, 0.f);
                    sum += v0 + v1;
                    if (WRITE_NEXT) {
                        const int d = 8 * jj + 2 * qn;
                        *(float2*)(x_next + ((size_t)b * 128 + o) * 32 + d) =
                            make_float2(v0, v1);
                    }
                }
                sum += __shfl_xor_sync(0xffffffffu, sum, 1);
                sum += __shfl_xor_sync(0xffffffffu, sum, 2);
                if (qn == 0) out[(size_t)b * 384 + out_off + o] = sum;
            }
        }
    }
}

// ---------------------------------------------------------------------------
extern "C" void kernel_launch(void* const* d_in, const int* in_sizes, int n_in,
                              void* d_out, int out_size)
{
    (void)in_sizes; (void)n_in; (void)out_size;
    const float* input = (const float*)d_in[0];
    const float* W0    = (const float*)d_in[1];
    const float* b0    = (const float*)d_in[2];
    const float* W1    = (const float*)d_in[3];
    const float* b1    = (const float*)d_in[4];
    const float* W2    = (const float*)d_in[5];
    const float* b2    = (const float*)d_in[6];
    float* out = (float*)d_out;

    float *x1, *x2; uint4 *w0p, *w1p, *w2p;
    cudaGetSymbolAddress((void**)&x1, g_x1);
    cudaGetSymbolAddress((void**)&x2, g_x2);
    cudaGetSymbolAddress((void**)&w0p, g_W0);
    cudaGetSymbolAddress((void**)&w1p, g_W1);
    cudaGetSymbolAddress((void**)&w2p, g_W2);

    cudaFuncSetAttribute((const void*)layer_mma<33,  64,  true,  true >, cudaFuncAttributeMaxDynamicSharedMemorySize, SMEM_TOTAL);
    cudaFuncSetAttribute((const void*)layer_mma<128, 128, false, true >, cudaFuncAttributeMaxDynamicSharedMemorySize, SMEM_TOTAL);
    cudaFuncSetAttribute((const void*)layer_mma<128, 128, false, false>, cudaFuncAttributeMaxDynamicSharedMemorySize, SMEM_TOTAL);

    init_pairs<<<(K0SYM + 255) / 256, 256>>>();
    prep_w0_sym<<<(128 * (K0SYM / 8) + 255) / 256, 256>>>(W0, w0p);
    prep_w<<<512, 256>>>(W1, w1p, 8192);
    prep_w<<<512, 256>>>(W2, w2p, 8192);

    dim3 grid(128), block(192);
    layer_mma<33,  64,  true,  true ><<<grid, block, SMEM_TOTAL>>>(input, input, w0p, b0, x1, out, 0);
    layer_mma<128, 128, false, true ><<<grid, block, SMEM_TOTAL>>>(x1,    input, w1p, b1, x2, out, 128);
    layer_mma<128, 128, false, false><<<grid, block, SMEM_TOTAL>>>(x2,    input, w2p, b2, nullptr, out, 256);
}

// round 14
// speedup vs baseline: 1.1756x; 1.1756x over previous
#include <cuda_runtime.h>
#include <cuda_bf16.h>
#include <cstdint>
#include <cstddef>

// ---------------------------------------------------------------------------
// pre[b,o,d] = sum_{h,f} W[o, h*64+f] * x[b,h,d] * inp[b,f,d] + bias[o]
// x_next = relu(pre);  out[:, off+o] = sum_d relu(pre);  3 chained layers.
// B=512, F=64, D=32, O=128.
//
// Round-14: FULLY FUSED 3-layer kernel. The layer chain is per-batch, so one
// CTA runs L0->L1->L2 for its 4 batches with x_next in SMEM (64KB buffer),
// replacing 2 kernel drains with 3 cheap __syncthreads. Base config = round-12
// winner: 8 consumer warps (m32xn64) + 4 producer warps, mbarrier pipeline
// (2 stages here for SMEM budget; 2==3 measured), layer-0 symmetry fold
// (K 4096->2112), 3-MMA bf16 split. Producers register-cache inp (the Z index
// is compile-time) -> no LDS in the L1/L2 Z loop.
// ---------------------------------------------------------------------------

#define SW128(o) ((o) ^ (((o) >> 3) & 0x70))

#define K0SYM   2112
#define K0REAL  2080
#define NT0     33
#define NT12    128

__device__ uint4 g_W0[33 * 32768 / 16];
__device__ uint4 g_W1[128 * 8192 * 4 / 16];
__device__ uint4 g_W2[128 * 8192 * 4 / 16];
__device__ unsigned short g_pair[K0SYM];

__device__ __forceinline__ uint32_t smem_u32(const void* p) {
    uint32_t a;
    asm("{ .reg .u64 t; cvta.to.shared.u64 t, %1; cvt.u32.u64 %0, t; }"
        : "=r"(a) : "l"(p));
    return a;
}

__device__ __forceinline__ void split2(float z0, float z1,
                                       uint32_t& hi, uint32_t& lo) {
    __nv_bfloat162 h = __floats2bfloat162_rn(z0, z1);
    float2 hf = __bfloat1622float2(h);
    __nv_bfloat162 l = __floats2bfloat162_rn(z0 - hf.x, z1 - hf.y);
    hi = reinterpret_cast<uint32_t&>(h);
    lo = reinterpret_cast<uint32_t&>(l);
}

__device__ __forceinline__ void ldsm4(uint32_t r[4], uint32_t addr) {
    asm volatile("ldmatrix.sync.aligned.m8n8.x4.shared.b16 {%0,%1,%2,%3}, [%4];"
                 : "=r"(r[0]), "=r"(r[1]), "=r"(r[2]), "=r"(r[3]) : "r"(addr));
}

__device__ __forceinline__ void mma_bf16(float c[4], const uint32_t a[4],
                                         uint32_t b0, uint32_t b1) {
    asm volatile(
        "mma.sync.aligned.m16n8k16.row.col.f32.bf16.bf16.f32 "
        "{%0,%1,%2,%3}, {%4,%5,%6,%7}, {%8,%9}, {%0,%1,%2,%3};"
        : "+f"(c[0]), "+f"(c[1]), "+f"(c[2]), "+f"(c[3])
        : "r"(a[0]), "r"(a[1]), "r"(a[2]), "r"(a[3]), "r"(b0), "r"(b1));
}

#define MBAR_INIT(a, c) \
    asm volatile("mbarrier.init.shared.b64 [%0], %1;" :: "r"(a), "r"(c) : "memory")
#define MBAR_ARRIVE(a) \
    asm volatile("mbarrier.arrive.release.cta.shared::cta.b64 _, [%0];" :: "r"(a) : "memory")
#define MBAR_WAIT(a, p) do { uint32_t _m = (a); uint32_t _p = (p); uint32_t _d;      \
    asm volatile("{\n\t.reg .pred q;\n\t"                                            \
        "mbarrier.try_wait.parity.acquire.cta.shared::cta.b64 q, [%1], %2;\n\t"      \
        "selp.b32 %0,1,0,q;\n\t}" : "=r"(_d) : "r"(_m), "r"(_p) : "memory");         \
    if (!_d) {                                                                       \
        asm volatile("{\n\t.reg .pred q;\n\t"                                        \
            "WL%=:\n\t"                                                              \
            "mbarrier.try_wait.parity.acquire.cta.shared::cta.b64 q, [%0], %1, 0x989680;\n\t" \
            "@q bra.uni WD%=;\n\t"                                                   \
            "bra.uni WL%=;\n\t"                                                      \
            "WD%=:\n\t}" :: "r"(_m), "r"(_p) : "memory");                            \
    } } while (0)

// --------------------------- pair table -------------------------------------
__global__ void init_pairs() {
    int k = blockIdx.x * 256 + threadIdx.x;
    if (k >= K0SYM) return;
    if (k < K0REAL) {
        int i = 0, base = 0;
        while (base + (64 - i) <= k) { base += 64 - i; i++; }
        int j = i + (k - base);
        g_pair[k] = (unsigned short)(i | (j << 8));
    } else {
        g_pair[k] = 0;
    }
}

// --------------------------- W prep -----------------------------------------
__global__ __launch_bounds__(256)
void prep_w(const float* __restrict__ W, uint4* __restrict__ dst, int K) {
    int idx = blockIdx.x * 256 + threadIdx.x;
    int cpr = K >> 3;
    if (idx >= 128 * cpr) return;
    int o = idx / cpr;
    int k = (idx % cpr) * 8;
    const float4* src = (const float4*)(W + (size_t)o * K + k);
    float4 v0 = src[0], v1 = src[1];
    float zf[8] = {v0.x, v0.y, v0.z, v0.w, v1.x, v1.y, v1.z, v1.w};
    uint32_t hi[4], lo[4];
#pragma unroll
    for (int p = 0; p < 4; p++) split2(zf[2 * p], zf[2 * p + 1], hi[p], lo[p]);
    char* base = (char*)dst + (size_t)(k >> 6) * 32768;
    uint32_t off = SW128((uint32_t)(o * 128 + (k & 63) * 2));
    *(uint4*)(base + off)         = make_uint4(hi[0], hi[1], hi[2], hi[3]);
    *(uint4*)(base + 16384 + off) = make_uint4(lo[0], lo[1], lo[2], lo[3]);
}

__global__ __launch_bounds__(256)
void prep_w0_sym(const float* __restrict__ W, uint4* __restrict__ dst) {
    int idx = blockIdx.x * 256 + threadIdx.x;
    if (idx >= 128 * (K0SYM / 8)) return;
    int o = idx / (K0SYM / 8);
    int k0 = (idx % (K0SYM / 8)) * 8;
    const float* Wo = W + (size_t)o * 4096;
    float zf[8];
#pragma unroll
    for (int t = 0; t < 8; t++) {
        int k = k0 + t;
        float c = 0.f;
        if (k < K0REAL) {
            int pr = g_pair[k];
            int i = pr & 255, j = pr >> 8;
            c = (i == j) ? Wo[i * 65] : (Wo[i * 64 + j] + Wo[j * 64 + i]);
        }
        zf[t] = c;
    }
    uint32_t hi[4], lo[4];
#pragma unroll
    for (int p = 0; p < 4; p++) split2(zf[2 * p], zf[2 * p + 1], hi[p], lo[p]);
    char* base = (char*)dst + (size_t)(k0 >> 6) * 32768;
    uint32_t off = SW128((uint32_t)(o * 128 + (k0 & 63) * 2));
    *(uint4*)(base + off)         = make_uint4(hi[0], hi[1], hi[2], hi[3]);
    *(uint4*)(base + 16384 + off) = make_uint4(lo[0], lo[1], lo[2], lo[3]);
}

// --------------------------- fused 3-layer kernel ---------------------------
// SMEM: [0,32768) inp_s; [32768,98304) xbuf (4 x 128 x 32 f32);
//       [98304 + s*65536), s=0..1: Whi Wlo Zhi Zlo;  [229376,229408) mbarriers
#define XBUF_OFF   32768
#define STAGE_OFF  98304
#define MB_OFF     229376
#define SMEM_TOTAL 229408

__global__ __launch_bounds__(384, 1)
void fused3(const float* __restrict__ inp,
            const float* __restrict__ bias0,
            const float* __restrict__ bias1,
            const float* __restrict__ bias2,
            float* __restrict__ out)
{
    extern __shared__ char smem[];
    const uint32_t sb = smem_u32(smem);
    float* inp_s = (float*)smem;
    float* xbuf  = (float*)(smem + XBUF_OFF);
    const int tid  = threadIdx.x;
    const int lane = tid & 31;
    const int w    = tid >> 5;
    const int b0   = blockIdx.x * 4;

    const uint32_t FULLB  = sb + MB_OFF;        // +8*s
    const uint32_t EMPTYB = sb + MB_OFF + 16;   // +8*s

    if (tid == 0) {
#pragma unroll
        for (int s = 0; s < 2; s++) {
            MBAR_INIT(FULLB + 8 * s, 4);     // 4 producer warps
            MBAR_INIT(EMPTYB + 8 * s, 8);    // 8 consumer warps
        }
    }
    {   // stage inp (2048 float4, 384 threads)
        const float4* src = (const float4*)(inp + (size_t)b0 * 2048);
        float4* dst = (float4*)inp_s;
        for (int i = tid; i < 2048; i += 384) dst[i] = src[i];
    }
    __syncthreads();

    if (w >= 8) {
        // ==================== PRODUCERS (warps 8-11) ====================
        const int n  = tid - 256;                  // 0..127
        const int bq = n >> 5;
        const int dd = n & 31;
        const float* ip = inp_s + (size_t)bq * 2048 + dd;
        const float* xp = xbuf + (size_t)bq * 4096 + dd;     // + it*32
        const uint32_t zrow  = (uint32_t)n * 128;
        const uint32_t zmask = (uint32_t)((n & 7) << 4);

        // Register-cache inp column (f = 0..63); Z index is compile-time in
        // the unrolled loops below so this never spills to local.
        float ipreg[64];
#pragma unroll
        for (int k = 0; k < 64; k++) ipreg[k] = ip[k * 32];

        int gt = 0;   // continuous tile counter across all layers

        auto produce = [&](const char* gW, int ntiles, bool sym) {
            for (int it = 0; it < ntiles; ++it, ++gt) {
                const int s = gt & 1;
                if (gt >= 2) MBAR_WAIT(EMPTYB + 8 * s,
                                       (uint32_t)(((gt >> 1) - 1) & 1));
                // W tile (128 thr x 256 B)
                {
                    uint32_t dsb = sb + STAGE_OFF + s * 65536 + n * 16;
                    const char* srcW = gW + (size_t)it * 32768 + n * 16;
#pragma unroll
                    for (int i = 0; i < 16; i++)
                        asm volatile("cp.async.cg.shared.global [%0], [%1], 16;"
                                     :: "r"(dsb + i * 2048), "l"(srcW + i * 2048));
                    asm volatile("cp.async.commit_group;");
                }
                // Z tile
                char* zp = smem + STAGE_OFF + s * 65536 + 32768;
                if (sym) {
#pragma unroll
                    for (int i = 0; i < 8; i++) {
                        float z[8];
#pragma unroll
                        for (int j = 0; j < 8; j++) {
                            int pr = __ldg(&g_pair[it * 64 + i * 8 + j]);
                            z[j] = ip[(pr & 255) * 32] * ip[(pr >> 8) * 32];
                        }
                        uint32_t hi[4], lo[4];
#pragma unroll
                        for (int p = 0; p < 4; p++)
                            split2(z[2 * p], z[2 * p + 1], hi[p], lo[p]);
                        uint32_t off = zrow + ((16u * i) ^ zmask);
                        *(uint4*)(zp + off)         = make_uint4(hi[0], hi[1], hi[2], hi[3]);
                        *(uint4*)(zp + 16384 + off) = make_uint4(lo[0], lo[1], lo[2], lo[3]);
                    }
                } else {
                    const float xv = xp[it * 32];    // x from SMEM xbuf
#pragma unroll
                    for (int i = 0; i < 8; i++) {
                        float z[8];
#pragma unroll
                        for (int j = 0; j < 8; j++) z[j] = xv * ipreg[i * 8 + j];
                        uint32_t hi[4], lo[4];
#pragma unroll
                        for (int p = 0; p < 4; p++)
                            split2(z[2 * p], z[2 * p + 1], hi[p], lo[p]);
                        uint32_t off = zrow + ((16u * i) ^ zmask);
                        *(uint4*)(zp + off)         = make_uint4(hi[0], hi[1], hi[2], hi[3]);
                        *(uint4*)(zp + 16384 + off) = make_uint4(lo[0], lo[1], lo[2], lo[3]);
                    }
                }
                asm volatile("cp.async.wait_group 0;");
                __syncwarp();
                if (lane == 0) MBAR_ARRIVE(FULLB + 8 * s);
            }
        };

        produce((const char*)g_W0, NT0, true);
        __syncthreads();                       // L0 epilogue done -> xbuf = x1
        produce((const char*)g_W1, NT12, false);
        __syncthreads();                       // L1 epilogue done -> xbuf = x2
        produce((const char*)g_W2, NT12, false);
        __syncthreads();                       // final (match consumers)
        return;
    }

    // ==================== CONSUMERS (warps 0-7), m32 x n64 ====================
    const int wm = w & 3;
    const int wn = w >> 2;

    const int g = lane >> 3;
    const uint32_t maskL = (uint32_t)((lane & 7) << 4);
    uint32_t aRow[2], bRow[4], aCol[4], bCol[4];
#pragma unroll
    for (int mi = 0; mi < 2; mi++)
        aRow[mi] = (uint32_t)((32 * wm + 16 * mi + (lane & 7) + (g & 1) * 8) * 128);
#pragma unroll
    for (int p = 0; p < 4; p++)
        bRow[p] = (uint32_t)((64 * wn + 16 * p + 8 * ((g >> 1) & 1) + (lane & 7)) * 128);
#pragma unroll
    for (int kk = 0; kk < 4; kk++) {
        aCol[kk] = ((uint32_t)(((g >> 1) & 1) * 16 + 32 * kk)) ^ maskL;
        bCol[kk] = ((uint32_t)((g & 1) * 16 + 32 * kk)) ^ maskL;
    }

    float C[2][8][4];
    int gt = 0;

    auto zeroC = [&]() {
#pragma unroll
        for (int i = 0; i < 2; i++)
#pragma unroll
            for (int j = 0; j < 8; j++)
#pragma unroll
                for (int q = 0; q < 4; q++) C[i][j][q] = 0.f;
    };

    auto consume = [&](int ntiles) {
        for (int t = 0; t < ntiles; ++t, ++gt) {
            const int s = gt & 1;
            MBAR_WAIT(FULLB + 8 * s, (uint32_t)((gt >> 1) & 1));
            const uint32_t st = sb + STAGE_OFF + s * 65536;
#pragma unroll
            for (int kk = 0; kk < 4; kk++) {
                uint32_t ah[2][4], al[2][4], bh[4][4], bl[4][4];
#pragma unroll
                for (int mi = 0; mi < 2; mi++) {
                    ldsm4(ah[mi], st + aRow[mi] + aCol[kk]);
                    ldsm4(al[mi], st + 16384 + aRow[mi] + aCol[kk]);
                }
#pragma unroll
                for (int p = 0; p < 4; p++) {
                    ldsm4(bh[p], st + 32768 + bRow[p] + bCol[kk]);
                    ldsm4(bl[p], st + 49152 + bRow[p] + bCol[kk]);
                }
#pragma unroll
                for (int p = 0; p < 4; p++)
#pragma unroll
                    for (int mi = 0; mi < 2; mi++)
#pragma unroll
                        for (int q = 0; q < 2; q++)
                            mma_bf16(C[mi][2 * p + q], ah[mi],
                                     bh[p][2 * q], bh[p][2 * q + 1]);
#pragma unroll
                for (int p = 0; p < 4; p++)
#pragma unroll
                    for (int mi = 0; mi < 2; mi++)
#pragma unroll
                        for (int q = 0; q < 2; q++)
                            mma_bf16(C[mi][2 * p + q], ah[mi],
                                     bl[p][2 * q], bl[p][2 * q + 1]);
#pragma unroll
                for (int p = 0; p < 4; p++)
#pragma unroll
                    for (int mi = 0; mi < 2; mi++)
#pragma unroll
                        for (int q = 0; q < 2; q++)
                            mma_bf16(C[mi][2 * p + q], al[mi],
                                     bh[p][2 * q], bh[p][2 * q + 1]);
            }
            __syncwarp();
            if (lane == 0) MBAR_ARRIVE(EMPTYB + 8 * s);
        }
    };

    const int mrow = lane >> 2;
    const int qn   = lane & 3;
    auto epilogue = [&](const float* bias, int out_off, bool write_x) {
#pragma unroll
        for (int mi = 0; mi < 2; mi++) {
#pragma unroll
            for (int h2 = 0; h2 < 2; h2++) {
                const int o = 32 * wm + 16 * mi + 8 * h2 + mrow;
                const float bv = __ldg(bias + o);
#pragma unroll
                for (int bl2 = 0; bl2 < 2; bl2++) {
                    const int bq = 2 * wn + bl2;
                    float sum = 0.f;
#pragma unroll
                    for (int jj = 0; jj < 4; jj++) {
                        const int j = 4 * bl2 + jj;
                        float v0 = fmaxf(C[mi][j][2 * h2]     + bv, 0.f);
                        float v1 = fmaxf(C[mi][j][2 * h2 + 1] + bv, 0.f);
                        sum += v0 + v1;
                        if (write_x) {
                            const int d = 8 * jj + 2 * qn;
                            *(float2*)(xbuf + ((size_t)bq * 128 + o) * 32 + d) =
                                make_float2(v0, v1);
                        }
                    }
                    sum += __shfl_xor_sync(0xffffffffu, sum, 1);
                    sum += __shfl_xor_sync(0xffffffffu, sum, 2);
                    if (qn == 0)
                        out[(size_t)(b0 + bq) * 384 + out_off + o] = sum;
                }
            }
        }
    };

    zeroC();
    consume(NT0);
    epilogue(bias0, 0, true);
    __syncthreads();

    zeroC();
    consume(NT12);
    epilogue(bias1, 128, true);
    __syncthreads();

    zeroC();
    consume(NT12);
    epilogue(bias2, 256, false);
    __syncthreads();
}

// ---------------------------------------------------------------------------
extern "C" void kernel_launch(void* const* d_in, const int* in_sizes, int n_in,
                              void* d_out, int out_size)
{
    (void)in_sizes; (void)n_in; (void)out_size;
    const float* input = (const float*)d_in[0];
    const float* W0    = (const float*)d_in[1];
    const float* b0    = (const float*)d_in[2];
    const float* W1    = (const float*)d_in[3];
    const float* b1    = (const float*)d_in[4];
    const float* W2    = (const float*)d_in[5];
    const float* b2    = (const float*)d_in[6];
    float* out = (float*)d_out;

    uint4 *w0p, *w1p, *w2p;
    cudaGetSymbolAddress((void**)&w0p, g_W0);
    cudaGetSymbolAddress((void**)&w1p, g_W1);
    cudaGetSymbolAddress((void**)&w2p, g_W2);

    cudaFuncSetAttribute(fused3, cudaFuncAttributeMaxDynamicSharedMemorySize,
                         SMEM_TOTAL);

    init_pairs<<<(K0SYM + 255) / 256, 256>>>();
    prep_w0_sym<<<(128 * (K0SYM / 8) + 255) / 256, 256>>>(W0, w0p);
    prep_w<<<512, 256>>>(W1, w1p, 8192);
    prep_w<<<512, 256>>>(W2, w2p, 8192);

    fused3<<<128, 384, SMEM_TOTAL>>>(input, b0, b1, b2, out);
}